// round 1
// baseline (speedup 1.0000x reference)
#include <cuda_runtime.h>
#include <math.h>

// ---------------------------------------------------------------------------
// Problem constants
// ---------------------------------------------------------------------------
#define BQ    8        // batch
#define NTOK  4096     // H*W
#define MTOT  32768    // BQ*NTOK
#define CDIM  512      // Q_DIM
#define TDIM  768      // T_DIM
#define KTXT  128      // K text tokens
#define HID   2048     // 4*Q_DIM
#define TOPM  5
#define TEMP_INV (1.0f/0.07f)
#define LN_EPS 1e-5f

// ---------------------------------------------------------------------------
// Scratch (device globals; no cudaMalloc allowed)
// ---------------------------------------------------------------------------
static __device__ float g_visln[MTOT * CDIM];          //  64 MB
static __device__ float g_q    [MTOT * TDIM];          // 100 MB (unnormalized Q)
static __device__ float g_keyt [BQ * KTXT * TDIM];     //   3 MB (l2-normalized)
static __device__ float g_value[BQ * KTXT * CDIM];     //   2 MB
static __device__ float g_X    [MTOT * CDIM];          //  64 MB (LN2 output)
static __device__ float g_hid  [MTOT * HID];           // 256 MB (gelu hidden)

// ---------------------------------------------------------------------------
// Kernel 1: text prep — keyt = l2norm(text), value = text @ Wv + bv
// grid: (BQ*KTXT/8) = 128 blocks, 256 threads. 8 text rows per block.
// ---------------------------------------------------------------------------
__global__ __launch_bounds__(256) void prep_text_kernel(
    const float* __restrict__ text, const float* __restrict__ Wv,
    const float* __restrict__ bv)
{
    __shared__ float ts[8][TDIM];   // 24 KB
    int tid = threadIdx.x, lane = tid & 31, warp = tid >> 5;
    int b  = blockIdx.x >> 4;          // blockIdx.x / 16
    int kb = (blockIdx.x & 15) * 8;
    const float* tb = text + ((size_t)b * KTXT + kb) * TDIM;

    #pragma unroll
    for (int i = 0; i < 24; i++) {
        int lin = tid + 256 * i;       // 0..6143
        int r = lin / TDIM, c = lin % TDIM;
        ts[r][c] = tb[(size_t)r * TDIM + c];
    }
    __syncthreads();

    // l2norm: warp w owns row w
    {
        int r = warp;
        float s = 0.f;
        for (int i = lane; i < TDIM; i += 32) { float v = ts[r][i]; s += v * v; }
        #pragma unroll
        for (int o = 16; o; o >>= 1) s += __shfl_xor_sync(0xffffffffu, s, o);
        float inv = 1.0f / fmaxf(sqrtf(s), 1e-12f);
        float* kr = g_keyt + ((size_t)b * KTXT + kb + r) * TDIM;
        for (int i = lane; i < TDIM; i += 32) kr[i] = ts[r][i] * inv;
    }

    // value = ts @ Wv + bv  (each thread: cols tid and tid+256, all 8 rows)
    float acc[8][2];
    #pragma unroll
    for (int r = 0; r < 8; r++) { acc[r][0] = 0.f; acc[r][1] = 0.f; }
    int c0 = tid, c1 = tid + 256;
    for (int t = 0; t < TDIM; t++) {
        float w0 = Wv[(size_t)t * CDIM + c0];
        float w1 = Wv[(size_t)t * CDIM + c1];
        #pragma unroll
        for (int r = 0; r < 8; r++) {
            float tv = ts[r][t];
            acc[r][0] += tv * w0;
            acc[r][1] += tv * w1;
        }
    }
    float bb0 = bv[c0], bb1 = bv[c1];
    #pragma unroll
    for (int r = 0; r < 8; r++) {
        float* vr = g_value + ((size_t)b * KTXT + kb + r) * CDIM;
        vr[c0] = acc[r][0] + bb0;
        vr[c1] = acc[r][1] + bb1;
    }
}

// ---------------------------------------------------------------------------
// Kernel 2: LayerNorm over last dim (512), warp-per-row, float4 I/O.
// grid: MTOT/8 blocks, 256 threads (8 warps).
// ---------------------------------------------------------------------------
__global__ __launch_bounds__(256) void ln_kernel(
    const float* __restrict__ in, const float* __restrict__ g,
    const float* __restrict__ be, float* __restrict__ out)
{
    int warp = threadIdx.x >> 5, lane = threadIdx.x & 31;
    size_t row = (size_t)blockIdx.x * 8 + warp;
    const float4* p = (const float4*)(in + row * CDIM);
    float4 x[4];
    float s = 0.f, s2 = 0.f;
    #pragma unroll
    for (int i = 0; i < 4; i++) {
        x[i] = p[lane + 32 * i];
        s  += x[i].x + x[i].y + x[i].z + x[i].w;
        s2 += x[i].x * x[i].x + x[i].y * x[i].y + x[i].z * x[i].z + x[i].w * x[i].w;
    }
    #pragma unroll
    for (int o = 16; o; o >>= 1) {
        s  += __shfl_xor_sync(0xffffffffu, s, o);
        s2 += __shfl_xor_sync(0xffffffffu, s2, o);
    }
    float mu  = s * (1.0f / CDIM);
    float var = s2 * (1.0f / CDIM) - mu * mu;
    float rs  = rsqrtf(var + LN_EPS);
    float4* o4 = (float4*)(out + row * CDIM);
    const float4* gp = (const float4*)g;
    const float4* bp = (const float4*)be;
    #pragma unroll
    for (int i = 0; i < 4; i++) {
        int c4 = lane + 32 * i;
        float4 gv = gp[c4], bv = bp[c4], r;
        r.x = (x[i].x - mu) * rs * gv.x + bv.x;
        r.y = (x[i].y - mu) * rs * gv.y + bv.y;
        r.z = (x[i].z - mu) * rs * gv.z + bv.z;
        r.w = (x[i].w - mu) * rs * gv.w + bv.w;
        o4[c4] = r;
    }
}

// ---------------------------------------------------------------------------
// SGEMM: C[M,N] = A[M,K] @ B[K,N] (+ bias, epilogue per MODE)
// 128x128 block tile, BK=8, 256 threads, 8x8 microtile.
// MODE 0: + bias            MODE 1: gelu(acc+bias)    MODE 2: acc+bias+Res
// Requires M%128==0, N%128==0, K%8==0 (all shapes here comply).
// ---------------------------------------------------------------------------
template <int MODE>
__global__ __launch_bounds__(256) void sgemm_kernel(
    const float* __restrict__ A, const float* __restrict__ B,
    const float* __restrict__ bias, const float* __restrict__ Res,
    float* __restrict__ Out, int M, int N, int Kd)
{
    __shared__ float As[8][128];
    __shared__ float Bs[8][128];
    int tid = threadIdx.x;
    int tx = tid & 15, ty = tid >> 4;
    int bn = blockIdx.x, bm = blockIdx.y;
    const float* Ab = A + (size_t)bm * 128 * Kd;
    const float* Bb = B + (size_t)bn * 128;
    int a_m = tid >> 1, a_k = (tid & 1) * 4;
    int b_k = tid >> 5, b_n = (tid & 31) * 4;

    float acc[8][8];
    #pragma unroll
    for (int i = 0; i < 8; i++)
        #pragma unroll
        for (int j = 0; j < 8; j++) acc[i][j] = 0.f;

    for (int k0 = 0; k0 < Kd; k0 += 8) {
        float4 av = *(const float4*)(Ab + (size_t)a_m * Kd + k0 + a_k);
        As[a_k + 0][a_m] = av.x;
        As[a_k + 1][a_m] = av.y;
        As[a_k + 2][a_m] = av.z;
        As[a_k + 3][a_m] = av.w;
        float4 bv = *(const float4*)(Bb + (size_t)(k0 + b_k) * N + b_n);
        *(float4*)&Bs[b_k][b_n] = bv;
        __syncthreads();
        #pragma unroll
        for (int k = 0; k < 8; k++) {
            float ar[8], br[8];
            #pragma unroll
            for (int i = 0; i < 4; i++) {
                ar[i]     = As[k][ty * 4 + i];
                ar[4 + i] = As[k][64 + ty * 4 + i];
                br[i]     = Bs[k][tx * 4 + i];
                br[4 + i] = Bs[k][64 + tx * 4 + i];
            }
            #pragma unroll
            for (int i = 0; i < 8; i++)
                #pragma unroll
                for (int j = 0; j < 8; j++) acc[i][j] += ar[i] * br[j];
        }
        __syncthreads();
    }

    #pragma unroll
    for (int gi = 0; gi < 2; gi++) {
        #pragma unroll
        for (int ii = 0; ii < 4; ii++) {
            int r = bm * 128 + gi * 64 + ty * 4 + ii;
            #pragma unroll
            for (int gj = 0; gj < 2; gj++) {
                int cb = bn * 128 + gj * 64 + tx * 4;
                float4 o;
                float* op = &o.x;
                #pragma unroll
                for (int jj = 0; jj < 4; jj++) {
                    int c = cb + jj;
                    float v = acc[gi * 4 + ii][gj * 4 + jj] + bias[c];
                    if (MODE == 1) v = v * normcdff(v);   // exact GELU
                    if (MODE == 2) v += Res[(size_t)r * N + c];
                    op[jj] = v;
                }
                *(float4*)(Out + (size_t)r * N + cb) = o;
            }
        }
    }
}

// ---------------------------------------------------------------------------
// Kernel 4: attention core.
// Per block: 16 tokens. sim = (q/||q||) @ keyt^T (GEMM-style), then per warp
// (2 rows each): top-5 via iterative warp-argmax, softmax/T over survivors,
// sparse attn@value (5 rows), +residual, LN2 -> g_X.
// grid: MTOT/16 = 2048 blocks, 256 threads.
// ---------------------------------------------------------------------------
__global__ __launch_bounds__(256) void attn_kernel(
    const float* __restrict__ resid, const float* __restrict__ g2,
    const float* __restrict__ be2)
{
    __shared__ float qs[16][32];
    __shared__ float ks[128][33];       // pad 33: conflict-free strided reads
    __shared__ float simbuf[16][128];
    __shared__ float invn[16];
    int tid = threadIdx.x, lane = tid & 31, warp = tid >> 5;
    int t0 = blockIdx.x * 16;
    int b  = t0 >> 12;                  // token / 4096

    // per-row inverse L2 norm of q (warp w: rows 2w, 2w+1)
    #pragma unroll
    for (int rr = 0; rr < 2; rr++) {
        int row = warp * 2 + rr;
        const float* qr = g_q + (size_t)(t0 + row) * TDIM;
        float s = 0.f;
        for (int i = lane; i < TDIM; i += 32) { float v = qr[i]; s += v * v; }
        #pragma unroll
        for (int o = 16; o; o >>= 1) s += __shfl_xor_sync(0xffffffffu, s, o);
        if (!lane) invn[row] = 1.0f / fmaxf(sqrtf(s), 1e-12f);
    }
    __syncthreads();

    // sim GEMM: 16 rows x 128 cols, K=768 in chunks of 32.
    // thread owns rows {warp, warp+8}, cols {lane+32j, j<4}
    float acc[2][4] = {};
    const float* Kb = g_keyt + (size_t)b * KTXT * TDIM;
    for (int kk = 0; kk < TDIM; kk += 32) {
        {
            int idx = tid * 2;
            int qr_ = idx >> 5, qk = idx & 31;
            float sc = invn[qr_];
            const float* qp = g_q + (size_t)(t0 + qr_) * TDIM + kk + qk;
            qs[qr_][qk]     = qp[0] * sc;
            qs[qr_][qk + 1] = qp[1] * sc;
        }
        #pragma unroll
        for (int i = 0; i < 16; i++) {
            int lin = tid + 256 * i;    // 0..4095
            int col = lin >> 5, k = lin & 31;
            ks[col][k] = Kb[(size_t)col * TDIM + kk + k];
        }
        __syncthreads();
        #pragma unroll
        for (int k = 0; k < 32; k++) {
            float q0 = qs[warp][k], q1 = qs[warp + 8][k];
            #pragma unroll
            for (int j = 0; j < 4; j++) {
                float kv = ks[lane + 32 * j][k];
                acc[0][j] += q0 * kv;
                acc[1][j] += q1 * kv;
            }
        }
        __syncthreads();
    }
    #pragma unroll
    for (int j = 0; j < 4; j++) {
        simbuf[warp][lane + 32 * j]     = acc[0][j];
        simbuf[warp + 8][lane + 32 * j] = acc[1][j];
    }
    __syncthreads();

    // epilogue: warp w handles rows 2w, 2w+1
    for (int rr = 0; rr < 2; rr++) {
        int row = warp * 2 + rr;
        float tv[4];
        #pragma unroll
        for (int j = 0; j < 4; j++) tv[j] = simbuf[row][lane + 32 * j];

        float mval[TOPM]; int midx[TOPM];
        #pragma unroll
        for (int it = 0; it < TOPM; it++) {
            float lm = tv[0]; int lj = 0;
            #pragma unroll
            for (int j = 1; j < 4; j++) if (tv[j] > lm) { lm = tv[j]; lj = j; }
            int li = lane + 32 * lj;
            #pragma unroll
            for (int o = 16; o; o >>= 1) {
                float ov = __shfl_xor_sync(0xffffffffu, lm, o);
                int   oi = __shfl_xor_sync(0xffffffffu, li, o);
                if (ov > lm || (ov == lm && oi < li)) { lm = ov; li = oi; }
            }
            mval[it] = lm; midx[it] = li;
            if ((li & 31) == lane) tv[li >> 5] = -INFINITY;
        }

        // softmax over the 5 survivors (all entries < thr -> exactly 0)
        float p[TOPM], psum = 0.f;
        #pragma unroll
        for (int it = 0; it < TOPM; it++) {
            p[it] = expf((mval[it] - mval[0]) * TEMP_INV);
            psum += p[it];
        }
        float rnorm = 1.0f / psum;

        // aligned = sum attn_k * value[k]  (sparse: 5 rows)
        float f[16];
        #pragma unroll
        for (int i = 0; i < 16; i++) f[i] = 0.f;
        const float* Vb = g_value + (size_t)b * KTXT * CDIM;
        #pragma unroll
        for (int it = 0; it < TOPM; it++) {
            const float* vr = Vb + (size_t)midx[it] * CDIM;
            float a_ = p[it] * rnorm;
            #pragma unroll
            for (int i = 0; i < 16; i++) f[i] += a_ * vr[lane + 32 * i];
        }

        // fused = residual + aligned; then LN2
        const float* rp = resid + (size_t)(t0 + row) * CDIM;
        float s = 0.f, s2 = 0.f;
        #pragma unroll
        for (int i = 0; i < 16; i++) {
            f[i] += rp[lane + 32 * i];
            s  += f[i];
            s2 += f[i] * f[i];
        }
        #pragma unroll
        for (int o = 16; o; o >>= 1) {
            s  += __shfl_xor_sync(0xffffffffu, s, o);
            s2 += __shfl_xor_sync(0xffffffffu, s2, o);
        }
        float mu  = s * (1.0f / CDIM);
        float var = s2 * (1.0f / CDIM) - mu * mu;
        float rstd = rsqrtf(var + LN_EPS);
        float* xp = g_X + (size_t)(t0 + row) * CDIM;
        #pragma unroll
        for (int i = 0; i < 16; i++) {
            int c = lane + 32 * i;
            xp[c] = (f[i] - mu) * rstd * g2[c] + be2[c];
        }
    }
}

// ---------------------------------------------------------------------------
// Launch
// ---------------------------------------------------------------------------
extern "C" void kernel_launch(void* const* d_in, const int* in_sizes, int n_in,
                              void* d_out, int out_size)
{
    const float* vis  = (const float*)d_in[0];
    const float* text = (const float*)d_in[1];
    const float* Wq   = (const float*)d_in[2];
    const float* bq   = (const float*)d_in[3];
    const float* Wv   = (const float*)d_in[4];
    const float* bv   = (const float*)d_in[5];
    const float* W1   = (const float*)d_in[6];
    const float* b1   = (const float*)d_in[7];
    const float* W2   = (const float*)d_in[8];
    const float* b2   = (const float*)d_in[9];
    const float* g1   = (const float*)d_in[10];
    const float* be1  = (const float*)d_in[11];
    const float* g2   = (const float*)d_in[12];
    const float* be2  = (const float*)d_in[13];
    float* out = (float*)d_out;

    float *p_visln, *p_q, *p_X, *p_hid;
    cudaGetSymbolAddress((void**)&p_visln, g_visln);
    cudaGetSymbolAddress((void**)&p_q,     g_q);
    cudaGetSymbolAddress((void**)&p_X,     g_X);
    cudaGetSymbolAddress((void**)&p_hid,   g_hid);

    // 1) text prep (keyt, value)
    prep_text_kernel<<<(BQ * KTXT) / 8, 256>>>(text, Wv, bv);
    // 2) LN1
    ln_kernel<<<MTOT / 8, 256>>>(vis, g1, be1, p_visln);
    // 3) Q = visln @ Wq + bq
    sgemm_kernel<0><<<dim3(TDIM / 128, MTOT / 128), 256>>>(
        p_visln, Wq, bq, nullptr, p_q, MTOT, TDIM, CDIM);
    // 4) attention + residual + LN2 -> X
    attn_kernel<<<MTOT / 16, 256>>>(vis, g2, be2);
    // 5) H = gelu(X @ W1 + b1)
    sgemm_kernel<1><<<dim3(HID / 128, MTOT / 128), 256>>>(
        p_X, W1, b1, nullptr, p_hid, MTOT, HID, CDIM);
    // 6) out = X + H @ W2 + b2
    sgemm_kernel<2><<<dim3(CDIM / 128, MTOT / 128), 256>>>(
        p_hid, W2, b2, p_X, out, MTOT, CDIM, HID);
}

// round 3
// speedup vs baseline: 1.8466x; 1.8466x over previous
#include <cuda_runtime.h>
#include <cuda_bf16.h>
#include <math.h>
#include <stdint.h>

// ---------------------------------------------------------------------------
// Problem constants
// ---------------------------------------------------------------------------
#define BQ    8        // batch
#define NTOK  4096     // H*W
#define MTOT  32768    // BQ*NTOK
#define CDIM  512      // Q_DIM
#define TDIM  768      // T_DIM
#define KTXT  128      // K text tokens
#define HID   2048     // 4*Q_DIM
#define TOPM  5
#define TEMP_INV (1.0f/0.07f)
#define LN_EPS 1e-5f

// ---------------------------------------------------------------------------
// Scratch (device globals; no cudaMalloc allowed)
// ---------------------------------------------------------------------------
static __device__ float g_visln[MTOT * CDIM];          //  64 MB
static __device__ float g_q    [MTOT * TDIM];          // 100 MB (unnormalized Q)
static __device__ float g_keyt [BQ * KTXT * TDIM];     //   3 MB (l2-normalized)
static __device__ float g_value[BQ * KTXT * CDIM];     //   2 MB
static __device__ float g_X    [MTOT * CDIM];          //  64 MB (LN2 output)
static __device__ float g_hid  [MTOT * HID];           // 256 MB (gelu hidden)

// ---------------------------------------------------------------------------
// bf16 split helpers
// ---------------------------------------------------------------------------
__device__ __forceinline__ void split2(float x, float y,
                                       uint32_t& hi, uint32_t& lo) {
    __nv_bfloat16 hx = __float2bfloat16_rn(x);
    __nv_bfloat16 hy = __float2bfloat16_rn(y);
    float rx = x - __bfloat162float(hx);
    float ry = y - __bfloat162float(hy);
    __nv_bfloat162 h2 = __halves2bfloat162(hx, hy);           // low = x (even k)
    __nv_bfloat162 l2 = __floats2bfloat162_rn(rx, ry);
    hi = *reinterpret_cast<uint32_t*>(&h2);
    lo = *reinterpret_cast<uint32_t*>(&l2);
}

__device__ __forceinline__ void mma_bf16(float* c, const uint32_t* a, const uint32_t* b) {
    asm volatile(
        "mma.sync.aligned.m16n8k16.row.col.f32.bf16.bf16.f32 "
        "{%0,%1,%2,%3}, {%4,%5,%6,%7}, {%8,%9}, {%0,%1,%2,%3};\n"
        : "+f"(c[0]), "+f"(c[1]), "+f"(c[2]), "+f"(c[3])
        : "r"(a[0]), "r"(a[1]), "r"(a[2]), "r"(a[3]), "r"(b[0]), "r"(b[1]));
}

// ---------------------------------------------------------------------------
// Kernel 1: text prep — keyt = l2norm(text), value = text @ Wv + bv
// ---------------------------------------------------------------------------
__global__ __launch_bounds__(256) void prep_text_kernel(
    const float* __restrict__ text, const float* __restrict__ Wv,
    const float* __restrict__ bv)
{
    __shared__ float ts[8][TDIM];   // 24 KB
    int tid = threadIdx.x, lane = tid & 31, warp = tid >> 5;
    int b  = blockIdx.x >> 4;
    int kb = (blockIdx.x & 15) * 8;
    const float* tb = text + ((size_t)b * KTXT + kb) * TDIM;

    #pragma unroll
    for (int i = 0; i < 24; i++) {
        int lin = tid + 256 * i;
        int r = lin / TDIM, c = lin % TDIM;
        ts[r][c] = tb[(size_t)r * TDIM + c];
    }
    __syncthreads();

    {
        int r = warp;
        float s = 0.f;
        for (int i = lane; i < TDIM; i += 32) { float v = ts[r][i]; s += v * v; }
        #pragma unroll
        for (int o = 16; o; o >>= 1) s += __shfl_xor_sync(0xffffffffu, s, o);
        float inv = 1.0f / fmaxf(sqrtf(s), 1e-12f);
        float* kr = g_keyt + ((size_t)b * KTXT + kb + r) * TDIM;
        for (int i = lane; i < TDIM; i += 32) kr[i] = ts[r][i] * inv;
    }

    float acc[8][2];
    #pragma unroll
    for (int r = 0; r < 8; r++) { acc[r][0] = 0.f; acc[r][1] = 0.f; }
    int c0 = tid, c1 = tid + 256;
    for (int t = 0; t < TDIM; t++) {
        float w0 = Wv[(size_t)t * CDIM + c0];
        float w1 = Wv[(size_t)t * CDIM + c1];
        #pragma unroll
        for (int r = 0; r < 8; r++) {
            float tv = ts[r][t];
            acc[r][0] += tv * w0;
            acc[r][1] += tv * w1;
        }
    }
    float bb0 = bv[c0], bb1 = bv[c1];
    #pragma unroll
    for (int r = 0; r < 8; r++) {
        float* vr = g_value + ((size_t)b * KTXT + kb + r) * CDIM;
        vr[c0] = acc[r][0] + bb0;
        vr[c1] = acc[r][1] + bb1;
    }
}

// ---------------------------------------------------------------------------
// Kernel 2: LayerNorm (warp-per-row, float4 I/O)
// ---------------------------------------------------------------------------
__global__ __launch_bounds__(256) void ln_kernel(
    const float* __restrict__ in, const float* __restrict__ g,
    const float* __restrict__ be, float* __restrict__ out)
{
    int warp = threadIdx.x >> 5, lane = threadIdx.x & 31;
    size_t row = (size_t)blockIdx.x * 8 + warp;
    const float4* p = (const float4*)(in + row * CDIM);
    float4 x[4];
    float s = 0.f, s2 = 0.f;
    #pragma unroll
    for (int i = 0; i < 4; i++) {
        x[i] = p[lane + 32 * i];
        s  += x[i].x + x[i].y + x[i].z + x[i].w;
        s2 += x[i].x * x[i].x + x[i].y * x[i].y + x[i].z * x[i].z + x[i].w * x[i].w;
    }
    #pragma unroll
    for (int o = 16; o; o >>= 1) {
        s  += __shfl_xor_sync(0xffffffffu, s, o);
        s2 += __shfl_xor_sync(0xffffffffu, s2, o);
    }
    float mu  = s * (1.0f / CDIM);
    float var = s2 * (1.0f / CDIM) - mu * mu;
    float rs  = rsqrtf(var + LN_EPS);
    float4* o4 = (float4*)(out + row * CDIM);
    const float4* gp = (const float4*)g;
    const float4* bp = (const float4*)be;
    #pragma unroll
    for (int i = 0; i < 4; i++) {
        int c4 = lane + 32 * i;
        float4 gv = gp[c4], bv = bp[c4], r;
        r.x = (x[i].x - mu) * rs * gv.x + bv.x;
        r.y = (x[i].y - mu) * rs * gv.y + bv.y;
        r.z = (x[i].z - mu) * rs * gv.z + bv.z;
        r.w = (x[i].w - mu) * rs * gv.w + bv.w;
        o4[c4] = r;
    }
}

// ---------------------------------------------------------------------------
// bf16x3 split-precision tensor-core GEMM: C = A[M,K] @ B[K,N] (+bias, MODE)
//   D += Ahi*Bhi + Ahi*Blo + Alo*Bhi      (error ~2^-18 on inputs)
// 128x128 block tile, BK=32, 256 threads = 8 warps (2m x 4n), warp 64x32,
// 4x4 m16n8k16 MMAs per k-step, 2 k-steps per tile, 3 passes (hi/lo).
// Smem: packed bf16x2 pairs along k, row stride 20 u32 -> fragment loads
// hit banks (20g+tg) mod 32 = all distinct -> conflict-free.
// MODE 0: +bias    MODE 1: gelu_exact(acc+bias)    MODE 2: acc+bias+Res
// Requires M%128==0, N%128==0, K%32==0.
// ---------------------------------------------------------------------------
template <int MODE>
__global__ __launch_bounds__(256) void tgemm_kernel(
    const float* __restrict__ A, const float* __restrict__ B,
    const float* __restrict__ bias, const float* __restrict__ Res,
    float* __restrict__ Out, int M, int N, int Kd)
{
    __shared__ uint32_t AsH[128][20];   // [m][k-pair]
    __shared__ uint32_t AsL[128][20];
    __shared__ uint32_t BsH[128][20];   // [n][k-pair]
    __shared__ uint32_t BsL[128][20];

    int tid = threadIdx.x, lane = tid & 31, warp = tid >> 5;
    int g  = lane >> 2, tg = lane & 3;
    int wm = warp >> 2, wn = warp & 3;          // 2 x 4 warp grid
    int m0 = wm * 64,  n0 = wn * 32;
    int bn = blockIdx.x, bm = blockIdx.y;

    const float* Ab = A + (size_t)bm * 128 * Kd;
    const float* Bb = B + (size_t)bn * 128;

    // A loader: row = tid>>1, k-halves: (tid&1)*16 + 4i (i<4)
    int a_r  = tid >> 1;
    int a_kb = (tid & 1) * 16;
    // B loader: n = 32*(warp&3)+lane, k-pairs kp = 8*(warp>>2)+j (j<8)
    int b_n  = 32 * (warp & 3) + lane;
    int b_kb = 8 * (warp >> 2);

    float acc[4][4][4];
    #pragma unroll
    for (int mi = 0; mi < 4; mi++)
        #pragma unroll
        for (int ni = 0; ni < 4; ni++)
            #pragma unroll
            for (int r = 0; r < 4; r++) acc[mi][ni][r] = 0.f;

    for (int k0 = 0; k0 < Kd; k0 += 32) {
        // ---- stage A (split bf16, pack pairs along k) ----
        #pragma unroll
        for (int i = 0; i < 4; i++) {
            float4 v = *(const float4*)(Ab + (size_t)a_r * Kd + k0 + a_kb + 4 * i);
            int kp = (a_kb >> 1) + 2 * i;
            uint32_t h0, l0, h1, l1;
            split2(v.x, v.y, h0, l0);
            split2(v.z, v.w, h1, l1);
            AsH[a_r][kp]     = h0;  AsL[a_r][kp]     = l0;
            AsH[a_r][kp + 1] = h1;  AsL[a_r][kp + 1] = l1;
        }
        // ---- stage B ----
        #pragma unroll
        for (int j = 0; j < 8; j++) {
            int kp = b_kb + j;
            int k  = k0 + 2 * kp;
            float x = Bb[(size_t)k       * N + b_n];
            float y = Bb[(size_t)(k + 1) * N + b_n];
            uint32_t h, l;
            split2(x, y, h, l);
            BsH[b_n][kp] = h;  BsL[b_n][kp] = l;
        }
        __syncthreads();

        #pragma unroll
        for (int ks = 0; ks < 2; ks++) {
            int kb = ks * 8;
            uint32_t ah[4][4], al[4][4], bh[4][2], bl[4][2];
            #pragma unroll
            for (int mi = 0; mi < 4; mi++) {
                int mb = m0 + mi * 16 + g;
                ah[mi][0] = AsH[mb][kb + tg];      al[mi][0] = AsL[mb][kb + tg];
                ah[mi][1] = AsH[mb + 8][kb + tg];  al[mi][1] = AsL[mb + 8][kb + tg];
                ah[mi][2] = AsH[mb][kb + 4 + tg];  al[mi][2] = AsL[mb][kb + 4 + tg];
                ah[mi][3] = AsH[mb + 8][kb + 4 + tg]; al[mi][3] = AsL[mb + 8][kb + 4 + tg];
            }
            #pragma unroll
            for (int ni = 0; ni < 4; ni++) {
                int nb = n0 + ni * 8 + g;
                bh[ni][0] = BsH[nb][kb + tg];      bl[ni][0] = BsL[nb][kb + tg];
                bh[ni][1] = BsH[nb][kb + 4 + tg];  bl[ni][1] = BsL[nb][kb + 4 + tg];
            }
            #pragma unroll
            for (int mi = 0; mi < 4; mi++)
                #pragma unroll
                for (int ni = 0; ni < 4; ni++) {
                    mma_bf16(acc[mi][ni], ah[mi], bh[ni]);
                    mma_bf16(acc[mi][ni], ah[mi], bl[ni]);
                    mma_bf16(acc[mi][ni], al[mi], bh[ni]);
                }
        }
        __syncthreads();
    }

    // epilogue: c0->(g,2tg) c1->(g,2tg+1) c2->(g+8,2tg) c3->(g+8,2tg+1)
    #pragma unroll
    for (int mi = 0; mi < 4; mi++) {
        #pragma unroll
        for (int half = 0; half < 2; half++) {
            int r = bm * 128 + m0 + mi * 16 + g + half * 8;
            #pragma unroll
            for (int ni = 0; ni < 4; ni++) {
                int c = bn * 128 + n0 + ni * 8 + 2 * tg;
                float v0 = acc[mi][ni][half * 2 + 0] + bias[c];
                float v1 = acc[mi][ni][half * 2 + 1] + bias[c + 1];
                if (MODE == 1) { v0 = v0 * normcdff(v0); v1 = v1 * normcdff(v1); }
                if (MODE == 2) {
                    v0 += Res[(size_t)r * N + c];
                    v1 += Res[(size_t)r * N + c + 1];
                }
                float2 o = { v0, v1 };
                *(float2*)(Out + (size_t)r * N + c) = o;
            }
        }
    }
}

// ---------------------------------------------------------------------------
// Kernel 4: attention core (fp32; proven in R1).
// ---------------------------------------------------------------------------
__global__ __launch_bounds__(256) void attn_kernel(
    const float* __restrict__ resid, const float* __restrict__ g2,
    const float* __restrict__ be2)
{
    __shared__ float qs[16][32];
    __shared__ float ks[128][33];
    __shared__ float simbuf[16][128];
    __shared__ float invn[16];
    int tid = threadIdx.x, lane = tid & 31, warp = tid >> 5;
    int t0 = blockIdx.x * 16;
    int b  = t0 >> 12;

    #pragma unroll
    for (int rr = 0; rr < 2; rr++) {
        int row = warp * 2 + rr;
        const float* qr = g_q + (size_t)(t0 + row) * TDIM;
        float s = 0.f;
        for (int i = lane; i < TDIM; i += 32) { float v = qr[i]; s += v * v; }
        #pragma unroll
        for (int o = 16; o; o >>= 1) s += __shfl_xor_sync(0xffffffffu, s, o);
        if (!lane) invn[row] = 1.0f / fmaxf(sqrtf(s), 1e-12f);
    }
    __syncthreads();

    float acc[2][4] = {};
    const float* Kb = g_keyt + (size_t)b * KTXT * TDIM;
    for (int kk = 0; kk < TDIM; kk += 32) {
        {
            int idx = tid * 2;
            int qr_ = idx >> 5, qk = idx & 31;
            float sc = invn[qr_];
            const float* qp = g_q + (size_t)(t0 + qr_) * TDIM + kk + qk;
            qs[qr_][qk]     = qp[0] * sc;
            qs[qr_][qk + 1] = qp[1] * sc;
        }
        #pragma unroll
        for (int i = 0; i < 16; i++) {
            int lin = tid + 256 * i;
            int col = lin >> 5, k = lin & 31;
            ks[col][k] = Kb[(size_t)col * TDIM + kk + k];
        }
        __syncthreads();
        #pragma unroll
        for (int k = 0; k < 32; k++) {
            float q0 = qs[warp][k], q1 = qs[warp + 8][k];
            #pragma unroll
            for (int j = 0; j < 4; j++) {
                float kv = ks[lane + 32 * j][k];
                acc[0][j] += q0 * kv;
                acc[1][j] += q1 * kv;
            }
        }
        __syncthreads();
    }
    #pragma unroll
    for (int j = 0; j < 4; j++) {
        simbuf[warp][lane + 32 * j]     = acc[0][j];
        simbuf[warp + 8][lane + 32 * j] = acc[1][j];
    }
    __syncthreads();

    for (int rr = 0; rr < 2; rr++) {
        int row = warp * 2 + rr;
        float tv[4];
        #pragma unroll
        for (int j = 0; j < 4; j++) tv[j] = simbuf[row][lane + 32 * j];

        float mval[TOPM]; int midx[TOPM];
        #pragma unroll
        for (int it = 0; it < TOPM; it++) {
            float lm = tv[0]; int lj = 0;
            #pragma unroll
            for (int j = 1; j < 4; j++) if (tv[j] > lm) { lm = tv[j]; lj = j; }
            int li = lane + 32 * lj;
            #pragma unroll
            for (int o = 16; o; o >>= 1) {
                float ov = __shfl_xor_sync(0xffffffffu, lm, o);
                int   oi = __shfl_xor_sync(0xffffffffu, li, o);
                if (ov > lm || (ov == lm && oi < li)) { lm = ov; li = oi; }
            }
            mval[it] = lm; midx[it] = li;
            if ((li & 31) == lane) tv[li >> 5] = -INFINITY;
        }

        float p[TOPM], psum = 0.f;
        #pragma unroll
        for (int it = 0; it < TOPM; it++) {
            p[it] = expf((mval[it] - mval[0]) * TEMP_INV);
            psum += p[it];
        }
        float rnorm = 1.0f / psum;

        float f[16];
        #pragma unroll
        for (int i = 0; i < 16; i++) f[i] = 0.f;
        const float* Vb = g_value + (size_t)b * KTXT * CDIM;
        #pragma unroll
        for (int it = 0; it < TOPM; it++) {
            const float* vr = Vb + (size_t)midx[it] * CDIM;
            float a_ = p[it] * rnorm;
            #pragma unroll
            for (int i = 0; i < 16; i++) f[i] += a_ * vr[lane + 32 * i];
        }

        const float* rp = resid + (size_t)(t0 + row) * CDIM;
        float s = 0.f, s2 = 0.f;
        #pragma unroll
        for (int i = 0; i < 16; i++) {
            f[i] += rp[lane + 32 * i];
            s  += f[i];
            s2 += f[i] * f[i];
        }
        #pragma unroll
        for (int o = 16; o; o >>= 1) {
            s  += __shfl_xor_sync(0xffffffffu, s, o);
            s2 += __shfl_xor_sync(0xffffffffu, s2, o);
        }
        float mu  = s * (1.0f / CDIM);
        float var = s2 * (1.0f / CDIM) - mu * mu;
        float rstd = rsqrtf(var + LN_EPS);
        float* xp = g_X + (size_t)(t0 + row) * CDIM;
        #pragma unroll
        for (int i = 0; i < 16; i++) {
            int c = lane + 32 * i;
            xp[c] = (f[i] - mu) * rstd * g2[c] + be2[c];
        }
    }
}

// ---------------------------------------------------------------------------
// Launch
// ---------------------------------------------------------------------------
extern "C" void kernel_launch(void* const* d_in, const int* in_sizes, int n_in,
                              void* d_out, int out_size)
{
    const float* vis  = (const float*)d_in[0];
    const float* text = (const float*)d_in[1];
    const float* Wq   = (const float*)d_in[2];
    const float* bq   = (const float*)d_in[3];
    const float* Wv   = (const float*)d_in[4];
    const float* bv   = (const float*)d_in[5];
    const float* W1   = (const float*)d_in[6];
    const float* b1   = (const float*)d_in[7];
    const float* W2   = (const float*)d_in[8];
    const float* b2   = (const float*)d_in[9];
    const float* g1   = (const float*)d_in[10];
    const float* be1  = (const float*)d_in[11];
    const float* g2   = (const float*)d_in[12];
    const float* be2  = (const float*)d_in[13];
    float* out = (float*)d_out;

    float *p_visln, *p_q, *p_X, *p_hid;
    cudaGetSymbolAddress((void**)&p_visln, g_visln);
    cudaGetSymbolAddress((void**)&p_q,     g_q);
    cudaGetSymbolAddress((void**)&p_X,     g_X);
    cudaGetSymbolAddress((void**)&p_hid,   g_hid);

    // 1) text prep (keyt, value)
    prep_text_kernel<<<(BQ * KTXT) / 8, 256>>>(text, Wv, bv);
    // 2) LN1
    ln_kernel<<<MTOT / 8, 256>>>(vis, g1, be1, p_visln);
    // 3) Q = visln @ Wq + bq   (bf16x3 tensor cores)
    tgemm_kernel<0><<<dim3(TDIM / 128, MTOT / 128), 256>>>(
        p_visln, Wq, bq, nullptr, p_q, MTOT, TDIM, CDIM);
    // 4) attention + residual + LN2 -> X
    attn_kernel<<<MTOT / 16, 256>>>(vis, g2, be2);
    // 5) H = gelu(X @ W1 + b1) (bf16x3 tensor cores)
    tgemm_kernel<1><<<dim3(HID / 128, MTOT / 128), 256>>>(
        p_X, W1, b1, nullptr, p_hid, MTOT, HID, CDIM);
    // 6) out = X + H @ W2 + b2 (bf16x3 tensor cores)
    tgemm_kernel<2><<<dim3(CDIM / 128, MTOT / 128), 256>>>(
        p_hid, W2, b2, p_X, out, MTOT, CDIM, HID);
}

// round 4
// speedup vs baseline: 1.8533x; 1.0036x over previous
#include <cuda_runtime.h>
#include <cuda_bf16.h>
#include <math.h>
#include <stdint.h>

// ---------------------------------------------------------------------------
// Problem constants
// ---------------------------------------------------------------------------
#define BQ    8        // batch
#define NTOK  4096     // H*W
#define MTOT  32768    // BQ*NTOK
#define CDIM  512      // Q_DIM
#define TDIM  768      // T_DIM
#define KTXT  128      // K text tokens
#define HID   2048     // 4*Q_DIM
#define TOPM  5
#define TEMP_INV (1.0f/0.07f)
#define LN_EPS 1e-5f

// ---------------------------------------------------------------------------
// Scratch (device globals; no cudaMalloc allowed)
// ---------------------------------------------------------------------------
static __device__ float g_visln[MTOT * CDIM];          //  64 MB
static __device__ float g_q    [MTOT * TDIM];          // 100 MB (unnormalized Q)
static __device__ float g_keyt [BQ * KTXT * TDIM];     //   3 MB (l2-normalized)
static __device__ float g_value[BQ * KTXT * CDIM];     //   2 MB
static __device__ float g_X    [MTOT * CDIM];          //  64 MB (LN2 output)
static __device__ float g_hid  [MTOT * HID];           // 256 MB (gelu hidden)

// ---------------------------------------------------------------------------
// bf16 split helpers
// ---------------------------------------------------------------------------
__device__ __forceinline__ void split2(float x, float y,
                                       uint32_t& hi, uint32_t& lo) {
    __nv_bfloat16 hx = __float2bfloat16_rn(x);
    __nv_bfloat16 hy = __float2bfloat16_rn(y);
    float rx = x - __bfloat162float(hx);
    float ry = y - __bfloat162float(hy);
    __nv_bfloat162 h2 = __halves2bfloat162(hx, hy);           // low = x (even k)
    __nv_bfloat162 l2 = __floats2bfloat162_rn(rx, ry);
    hi = *reinterpret_cast<uint32_t*>(&h2);
    lo = *reinterpret_cast<uint32_t*>(&l2);
}

__device__ __forceinline__ void mma_bf16(float* c, const uint32_t* a, const uint32_t* b) {
    asm volatile(
        "mma.sync.aligned.m16n8k16.row.col.f32.bf16.bf16.f32 "
        "{%0,%1,%2,%3}, {%4,%5,%6,%7}, {%8,%9}, {%0,%1,%2,%3};\n"
        : "+f"(c[0]), "+f"(c[1]), "+f"(c[2]), "+f"(c[3])
        : "r"(a[0]), "r"(a[1]), "r"(a[2]), "r"(a[3]), "r"(b[0]), "r"(b[1]));
}

// ---------------------------------------------------------------------------
// Kernel 1: text prep — keyt = l2norm(text), value = text @ Wv + bv
// ---------------------------------------------------------------------------
__global__ __launch_bounds__(256) void prep_text_kernel(
    const float* __restrict__ text, const float* __restrict__ Wv,
    const float* __restrict__ bv)
{
    __shared__ float ts[8][TDIM];   // 24 KB
    int tid = threadIdx.x, lane = tid & 31, warp = tid >> 5;
    int b  = blockIdx.x >> 4;
    int kb = (blockIdx.x & 15) * 8;
    const float* tb = text + ((size_t)b * KTXT + kb) * TDIM;

    #pragma unroll
    for (int i = 0; i < 24; i++) {
        int lin = tid + 256 * i;
        int r = lin / TDIM, c = lin % TDIM;
        ts[r][c] = tb[(size_t)r * TDIM + c];
    }
    __syncthreads();

    {
        int r = warp;
        float s = 0.f;
        for (int i = lane; i < TDIM; i += 32) { float v = ts[r][i]; s += v * v; }
        #pragma unroll
        for (int o = 16; o; o >>= 1) s += __shfl_xor_sync(0xffffffffu, s, o);
        float inv = 1.0f / fmaxf(sqrtf(s), 1e-12f);
        float* kr = g_keyt + ((size_t)b * KTXT + kb + r) * TDIM;
        for (int i = lane; i < TDIM; i += 32) kr[i] = ts[r][i] * inv;
    }

    float acc[8][2];
    #pragma unroll
    for (int r = 0; r < 8; r++) { acc[r][0] = 0.f; acc[r][1] = 0.f; }
    int c0 = tid, c1 = tid + 256;
    for (int t = 0; t < TDIM; t++) {
        float w0 = Wv[(size_t)t * CDIM + c0];
        float w1 = Wv[(size_t)t * CDIM + c1];
        #pragma unroll
        for (int r = 0; r < 8; r++) {
            float tv = ts[r][t];
            acc[r][0] += tv * w0;
            acc[r][1] += tv * w1;
        }
    }
    float bb0 = bv[c0], bb1 = bv[c1];
    #pragma unroll
    for (int r = 0; r < 8; r++) {
        float* vr = g_value + ((size_t)b * KTXT + kb + r) * CDIM;
        vr[c0] = acc[r][0] + bb0;
        vr[c1] = acc[r][1] + bb1;
    }
}

// ---------------------------------------------------------------------------
// Kernel 2: LayerNorm (warp-per-row, float4 I/O)
// ---------------------------------------------------------------------------
__global__ __launch_bounds__(256) void ln_kernel(
    const float* __restrict__ in, const float* __restrict__ g,
    const float* __restrict__ be, float* __restrict__ out)
{
    int warp = threadIdx.x >> 5, lane = threadIdx.x & 31;
    size_t row = (size_t)blockIdx.x * 8 + warp;
    const float4* p = (const float4*)(in + row * CDIM);
    float4 x[4];
    float s = 0.f, s2 = 0.f;
    #pragma unroll
    for (int i = 0; i < 4; i++) {
        x[i] = p[lane + 32 * i];
        s  += x[i].x + x[i].y + x[i].z + x[i].w;
        s2 += x[i].x * x[i].x + x[i].y * x[i].y + x[i].z * x[i].z + x[i].w * x[i].w;
    }
    #pragma unroll
    for (int o = 16; o; o >>= 1) {
        s  += __shfl_xor_sync(0xffffffffu, s, o);
        s2 += __shfl_xor_sync(0xffffffffu, s2, o);
    }
    float mu  = s * (1.0f / CDIM);
    float var = s2 * (1.0f / CDIM) - mu * mu;
    float rs  = rsqrtf(var + LN_EPS);
    float4* o4 = (float4*)(out + row * CDIM);
    const float4* gp = (const float4*)g;
    const float4* bp = (const float4*)be;
    #pragma unroll
    for (int i = 0; i < 4; i++) {
        int c4 = lane + 32 * i;
        float4 gv = gp[c4], bv = bp[c4], r;
        r.x = (x[i].x - mu) * rs * gv.x + bv.x;
        r.y = (x[i].y - mu) * rs * gv.y + bv.y;
        r.z = (x[i].z - mu) * rs * gv.z + bv.z;
        r.w = (x[i].w - mu) * rs * gv.w + bv.w;
        o4[c4] = r;
    }
}

// ---------------------------------------------------------------------------
// bf16x3 split-precision tensor-core GEMM: C = A[M,K] @ B[K,N] (+bias, MODE)
//   D += Ahi*Bhi + Ahi*Blo + Alo*Bhi      (error ~2^-18 on inputs)
// 128x128 block tile, BK=32, 256 threads = 8 warps (2m x 4n), warp 64x32,
// 4x4 m16n8k16 MMAs per k-step, 2 k-steps per tile, 3 passes (hi/lo).
// Smem: packed bf16x2 pairs along k, row stride 20 u32 -> fragment loads
// hit banks (20g+tg) mod 32 = all distinct -> conflict-free.
// MODE 0: +bias    MODE 1: gelu_exact(acc+bias)    MODE 2: acc+bias+Res
// Requires M%128==0, N%128==0, K%32==0.
// ---------------------------------------------------------------------------
template <int MODE>
__global__ __launch_bounds__(256) void tgemm_kernel(
    const float* __restrict__ A, const float* __restrict__ B,
    const float* __restrict__ bias, const float* __restrict__ Res,
    float* __restrict__ Out, int M, int N, int Kd)
{
    __shared__ uint32_t AsH[128][20];   // [m][k-pair]
    __shared__ uint32_t AsL[128][20];
    __shared__ uint32_t BsH[128][20];   // [n][k-pair]
    __shared__ uint32_t BsL[128][20];

    int tid = threadIdx.x, lane = tid & 31, warp = tid >> 5;
    int g  = lane >> 2, tg = lane & 3;
    int wm = warp >> 2, wn = warp & 3;          // 2 x 4 warp grid
    int m0 = wm * 64,  n0 = wn * 32;
    int bn = blockIdx.x, bm = blockIdx.y;

    const float* Ab = A + (size_t)bm * 128 * Kd;
    const float* Bb = B + (size_t)bn * 128;

    // A loader: row = tid>>1, k-halves: (tid&1)*16 + 4i (i<4)
    int a_r  = tid >> 1;
    int a_kb = (tid & 1) * 16;
    // B loader: n = 32*(warp&3)+lane, k-pairs kp = 8*(warp>>2)+j (j<8)
    int b_n  = 32 * (warp & 3) + lane;
    int b_kb = 8 * (warp >> 2);

    float acc[4][4][4];
    #pragma unroll
    for (int mi = 0; mi < 4; mi++)
        #pragma unroll
        for (int ni = 0; ni < 4; ni++)
            #pragma unroll
            for (int r = 0; r < 4; r++) acc[mi][ni][r] = 0.f;

    for (int k0 = 0; k0 < Kd; k0 += 32) {
        // ---- stage A (split bf16, pack pairs along k) ----
        #pragma unroll
        for (int i = 0; i < 4; i++) {
            float4 v = *(const float4*)(Ab + (size_t)a_r * Kd + k0 + a_kb + 4 * i);
            int kp = (a_kb >> 1) + 2 * i;
            uint32_t h0, l0, h1, l1;
            split2(v.x, v.y, h0, l0);
            split2(v.z, v.w, h1, l1);
            AsH[a_r][kp]     = h0;  AsL[a_r][kp]     = l0;
            AsH[a_r][kp + 1] = h1;  AsL[a_r][kp + 1] = l1;
        }
        // ---- stage B ----
        #pragma unroll
        for (int j = 0; j < 8; j++) {
            int kp = b_kb + j;
            int k  = k0 + 2 * kp;
            float x = Bb[(size_t)k       * N + b_n];
            float y = Bb[(size_t)(k + 1) * N + b_n];
            uint32_t h, l;
            split2(x, y, h, l);
            BsH[b_n][kp] = h;  BsL[b_n][kp] = l;
        }
        __syncthreads();

        #pragma unroll
        for (int ks = 0; ks < 2; ks++) {
            int kb = ks * 8;
            uint32_t ah[4][4], al[4][4], bh[4][2], bl[4][2];
            #pragma unroll
            for (int mi = 0; mi < 4; mi++) {
                int mb = m0 + mi * 16 + g;
                ah[mi][0] = AsH[mb][kb + tg];      al[mi][0] = AsL[mb][kb + tg];
                ah[mi][1] = AsH[mb + 8][kb + tg];  al[mi][1] = AsL[mb + 8][kb + tg];
                ah[mi][2] = AsH[mb][kb + 4 + tg];  al[mi][2] = AsL[mb][kb + 4 + tg];
                ah[mi][3] = AsH[mb + 8][kb + 4 + tg]; al[mi][3] = AsL[mb + 8][kb + 4 + tg];
            }
            #pragma unroll
            for (int ni = 0; ni < 4; ni++) {
                int nb = n0 + ni * 8 + g;
                bh[ni][0] = BsH[nb][kb + tg];      bl[ni][0] = BsL[nb][kb + tg];
                bh[ni][1] = BsH[nb][kb + 4 + tg];  bl[ni][1] = BsL[nb][kb + 4 + tg];
            }
            #pragma unroll
            for (int mi = 0; mi < 4; mi++)
                #pragma unroll
                for (int ni = 0; ni < 4; ni++) {
                    mma_bf16(acc[mi][ni], ah[mi], bh[ni]);
                    mma_bf16(acc[mi][ni], ah[mi], bl[ni]);
                    mma_bf16(acc[mi][ni], al[mi], bh[ni]);
                }
        }
        __syncthreads();
    }

    // epilogue: c0->(g,2tg) c1->(g,2tg+1) c2->(g+8,2tg) c3->(g+8,2tg+1)
    #pragma unroll
    for (int mi = 0; mi < 4; mi++) {
        #pragma unroll
        for (int half = 0; half < 2; half++) {
            int r = bm * 128 + m0 + mi * 16 + g + half * 8;
            #pragma unroll
            for (int ni = 0; ni < 4; ni++) {
                int c = bn * 128 + n0 + ni * 8 + 2 * tg;
                float v0 = acc[mi][ni][half * 2 + 0] + bias[c];
                float v1 = acc[mi][ni][half * 2 + 1] + bias[c + 1];
                if (MODE == 1) { v0 = v0 * normcdff(v0); v1 = v1 * normcdff(v1); }
                if (MODE == 2) {
                    v0 += Res[(size_t)r * N + c];
                    v1 += Res[(size_t)r * N + c + 1];
                }
                float2 o = { v0, v1 };
                *(float2*)(Out + (size_t)r * N + c) = o;
            }
        }
    }
}

// ---------------------------------------------------------------------------
// Kernel 4: attention core (fp32; proven in R1).
// ---------------------------------------------------------------------------
__global__ __launch_bounds__(256) void attn_kernel(
    const float* __restrict__ resid, const float* __restrict__ g2,
    const float* __restrict__ be2)
{
    __shared__ float qs[16][32];
    __shared__ float ks[128][33];
    __shared__ float simbuf[16][128];
    __shared__ float invn[16];
    int tid = threadIdx.x, lane = tid & 31, warp = tid >> 5;
    int t0 = blockIdx.x * 16;
    int b  = t0 >> 12;

    #pragma unroll
    for (int rr = 0; rr < 2; rr++) {
        int row = warp * 2 + rr;
        const float* qr = g_q + (size_t)(t0 + row) * TDIM;
        float s = 0.f;
        for (int i = lane; i < TDIM; i += 32) { float v = qr[i]; s += v * v; }
        #pragma unroll
        for (int o = 16; o; o >>= 1) s += __shfl_xor_sync(0xffffffffu, s, o);
        if (!lane) invn[row] = 1.0f / fmaxf(sqrtf(s), 1e-12f);
    }
    __syncthreads();

    float acc[2][4] = {};
    const float* Kb = g_keyt + (size_t)b * KTXT * TDIM;
    for (int kk = 0; kk < TDIM; kk += 32) {
        {
            int idx = tid * 2;
            int qr_ = idx >> 5, qk = idx & 31;
            float sc = invn[qr_];
            const float* qp = g_q + (size_t)(t0 + qr_) * TDIM + kk + qk;
            qs[qr_][qk]     = qp[0] * sc;
            qs[qr_][qk + 1] = qp[1] * sc;
        }
        #pragma unroll
        for (int i = 0; i < 16; i++) {
            int lin = tid + 256 * i;
            int col = lin >> 5, k = lin & 31;
            ks[col][k] = Kb[(size_t)col * TDIM + kk + k];
        }
        __syncthreads();
        #pragma unroll
        for (int k = 0; k < 32; k++) {
            float q0 = qs[warp][k], q1 = qs[warp + 8][k];
            #pragma unroll
            for (int j = 0; j < 4; j++) {
                float kv = ks[lane + 32 * j][k];
                acc[0][j] += q0 * kv;
                acc[1][j] += q1 * kv;
            }
        }
        __syncthreads();
    }
    #pragma unroll
    for (int j = 0; j < 4; j++) {
        simbuf[warp][lane + 32 * j]     = acc[0][j];
        simbuf[warp + 8][lane + 32 * j] = acc[1][j];
    }
    __syncthreads();

    for (int rr = 0; rr < 2; rr++) {
        int row = warp * 2 + rr;
        float tv[4];
        #pragma unroll
        for (int j = 0; j < 4; j++) tv[j] = simbuf[row][lane + 32 * j];

        float mval[TOPM]; int midx[TOPM];
        #pragma unroll
        for (int it = 0; it < TOPM; it++) {
            float lm = tv[0]; int lj = 0;
            #pragma unroll
            for (int j = 1; j < 4; j++) if (tv[j] > lm) { lm = tv[j]; lj = j; }
            int li = lane + 32 * lj;
            #pragma unroll
            for (int o = 16; o; o >>= 1) {
                float ov = __shfl_xor_sync(0xffffffffu, lm, o);
                int   oi = __shfl_xor_sync(0xffffffffu, li, o);
                if (ov > lm || (ov == lm && oi < li)) { lm = ov; li = oi; }
            }
            mval[it] = lm; midx[it] = li;
            if ((li & 31) == lane) tv[li >> 5] = -INFINITY;
        }

        float p[TOPM], psum = 0.f;
        #pragma unroll
        for (int it = 0; it < TOPM; it++) {
            p[it] = expf((mval[it] - mval[0]) * TEMP_INV);
            psum += p[it];
        }
        float rnorm = 1.0f / psum;

        float f[16];
        #pragma unroll
        for (int i = 0; i < 16; i++) f[i] = 0.f;
        const float* Vb = g_value + (size_t)b * KTXT * CDIM;
        #pragma unroll
        for (int it = 0; it < TOPM; it++) {
            const float* vr = Vb + (size_t)midx[it] * CDIM;
            float a_ = p[it] * rnorm;
            #pragma unroll
            for (int i = 0; i < 16; i++) f[i] += a_ * vr[lane + 32 * i];
        }

        const float* rp = resid + (size_t)(t0 + row) * CDIM;
        float s = 0.f, s2 = 0.f;
        #pragma unroll
        for (int i = 0; i < 16; i++) {
            f[i] += rp[lane + 32 * i];
            s  += f[i];
            s2 += f[i] * f[i];
        }
        #pragma unroll
        for (int o = 16; o; o >>= 1) {
            s  += __shfl_xor_sync(0xffffffffu, s, o);
            s2 += __shfl_xor_sync(0xffffffffu, s2, o);
        }
        float mu  = s * (1.0f / CDIM);
        float var = s2 * (1.0f / CDIM) - mu * mu;
        float rstd = rsqrtf(var + LN_EPS);
        float* xp = g_X + (size_t)(t0 + row) * CDIM;
        #pragma unroll
        for (int i = 0; i < 16; i++) {
            int c = lane + 32 * i;
            xp[c] = (f[i] - mu) * rstd * g2[c] + be2[c];
        }
    }
}

// ---------------------------------------------------------------------------
// Launch
// ---------------------------------------------------------------------------
extern "C" void kernel_launch(void* const* d_in, const int* in_sizes, int n_in,
                              void* d_out, int out_size)
{
    const float* vis  = (const float*)d_in[0];
    const float* text = (const float*)d_in[1];
    const float* Wq   = (const float*)d_in[2];
    const float* bq   = (const float*)d_in[3];
    const float* Wv   = (const float*)d_in[4];
    const float* bv   = (const float*)d_in[5];
    const float* W1   = (const float*)d_in[6];
    const float* b1   = (const float*)d_in[7];
    const float* W2   = (const float*)d_in[8];
    const float* b2   = (const float*)d_in[9];
    const float* g1   = (const float*)d_in[10];
    const float* be1  = (const float*)d_in[11];
    const float* g2   = (const float*)d_in[12];
    const float* be2  = (const float*)d_in[13];
    float* out = (float*)d_out;

    float *p_visln, *p_q, *p_X, *p_hid;
    cudaGetSymbolAddress((void**)&p_visln, g_visln);
    cudaGetSymbolAddress((void**)&p_q,     g_q);
    cudaGetSymbolAddress((void**)&p_X,     g_X);
    cudaGetSymbolAddress((void**)&p_hid,   g_hid);

    // 1) text prep (keyt, value)
    prep_text_kernel<<<(BQ * KTXT) / 8, 256>>>(text, Wv, bv);
    // 2) LN1
    ln_kernel<<<MTOT / 8, 256>>>(vis, g1, be1, p_visln);
    // 3) Q = visln @ Wq + bq   (bf16x3 tensor cores)
    tgemm_kernel<0><<<dim3(TDIM / 128, MTOT / 128), 256>>>(
        p_visln, Wq, bq, nullptr, p_q, MTOT, TDIM, CDIM);
    // 4) attention + residual + LN2 -> X
    attn_kernel<<<MTOT / 16, 256>>>(vis, g2, be2);
    // 5) H = gelu(X @ W1 + b1) (bf16x3 tensor cores)
    tgemm_kernel<1><<<dim3(HID / 128, MTOT / 128), 256>>>(
        p_X, W1, b1, nullptr, p_hid, MTOT, HID, CDIM);
    // 6) out = X + H @ W2 + b2 (bf16x3 tensor cores)
    tgemm_kernel<2><<<dim3(CDIM / 128, MTOT / 128), 256>>>(
        p_hid, W2, b2, p_X, out, MTOT, CDIM, HID);
}